// round 15
// baseline (speedup 1.0000x reference)
#include <cuda_runtime.h>

// ----------------------------------------------------------------------------
// RNNDecoder: 3-layer GRU (H=128), T=256, B=1024, fc head (out=2).
//
// R13: 128 CTAs x 512 threads = TWO independent 256-thread groups per CTA,
// each with its OWN named barrier (bar.sync 1/2, 256) and its own 4 batch
// rows. Diagnosis R3-R12: FMA pipe idle ~50%/cell because all warps share one
// barrier domain and march in phase (in-order issue defeats intra-thread
// overlap). Two in-CTA domains drift out of phase, so one group's FFMA2
// stream fills the other's combine/barrier troughs, while sharing the SM's
// L1 weight stream (unlike R10's 2-CTA attempt) and keeping the grid
// balanced at 1 CTA/SM.
//   - Per group: thread (kh,u) owns unit u's r,z,n rows over K-half kh.
//     768 FFMA2/thread/cell, batch-pair f32x2, dup2 on the idle alu pipe.
//   - 2-way exchange (4 ST.64 + 4 LD.64); 2 named barriers/cell.
//   - Weights pre-transposed, double-buffered one chunk ahead.
// ----------------------------------------------------------------------------

namespace {
constexpr int LAYERS = 3;
constexpr int H      = 128;
constexpr int G3     = 3 * H;
constexpr int T      = 256;
constexpr int GB     = 4;          // batches per group
constexpr int NTHR   = 512;
constexpr int NBLK   = 128;        // 1024 / 8
constexpr int KCH    = 16;         // float4 K-chunks per K-half
constexpr int GT     = 256;        // threads per group
}

typedef unsigned long long ull;

// Transposed weights: [l][kkp][g(r,z,n)][t] float4, t = kh*128 + u.
__device__ float4 g_wih[LAYERS * KCH * 3 * GT];
__device__ float4 g_whh[LAYERS * KCH * 3 * GT];

__global__ void prep_kernel(const float* __restrict__ wih,
                            const float* __restrict__ whh) {
  const int PER = LAYERS * KCH * 3 * GT;
  int idx = blockIdx.x * blockDim.x + threadIdx.x;
  if (idx >= 2 * PER) return;
  int arr = idx / PER;
  int r   = idx % PER;
  int t   = r % GT;
  int g   = (r / GT) % 3;
  int kkp = (r / (GT * 3)) % KCH;
  int l   = r / (GT * 3 * KCH);
  int u   = t & 127, kh = t >> 7;
  int k4  = kh * KCH + kkp;
  const float* src = (arr ? whh : wih) + (l * G3 + g * 128 + u) * H + k4 * 4;
  float4* dst = arr ? g_whh : g_wih;
  dst[((l * KCH + kkp) * 3 + g) * GT + t] =
      *reinterpret_cast<const float4*>(src);
}

__device__ __forceinline__ void ffma2(ull& a, ull w, ull x) {
  asm("fma.rn.f32x2 %0, %1, %2, %0;" : "+l"(a) : "l"(w), "l"(x));
}
__device__ __forceinline__ void fadd2(ull& a, ull b) {
  asm("add.rn.f32x2 %0, %0, %1;" : "+l"(a) : "l"(b));
}
__device__ __forceinline__ ull dup2(float w) {
  ull r;
  asm("mov.b64 %0, {%1, %1};" : "=l"(r) : "f"(w));
  return r;
}
__device__ __forceinline__ float2 unpk(ull v) {
  float lo, hi;
  asm("mov.b64 {%0, %1}, %2;" : "=f"(lo), "=f"(hi) : "l"(v));
  return make_float2(lo, hi);
}
__device__ __forceinline__ ull pack2(float lo, float hi) {
  ull r;
  asm("mov.b64 %0, {%1, %2};" : "=l"(r) : "f"(lo), "f"(hi));
  return r;
}
__device__ __forceinline__ float sigm(float x) {
  return __fdividef(1.0f, 1.0f + __expf(-x));
}
__device__ __forceinline__ float tanh_fast(float v) {
  float a = fabsf(v);
  float e = __expf(-2.0f * a);
  float r = __fdividef(1.0f - e, 1.0f + e);
  return copysignf(r, v);
}
__device__ __forceinline__ float comp(const float4& v, int e) {
  return e == 0 ? v.x : e == 1 ? v.y : e == 2 ? v.z : v.w;
}
__device__ __forceinline__ void gbar(int id) {
  asm volatile("bar.sync %0, %1;" :: "r"(id), "r"(GT) : "memory");
}

// Half-gemv over this thread's 64-k half: 3 gate rows x 4 batches (2 pairs).
// Zero-inits acc. 48 LDG.128, 64 LDS.128, 384 FFMA2 per call.
__device__ __forceinline__ void half_gemv(const float* __restrict__ act,
                                          const float4* __restrict__ wp,
                                          ull (&acc)[3][2]) {
#pragma unroll
  for (int g = 0; g < 3; g++) {
    acc[g][0] = 0ull;
    acc[g][1] = 0ull;
  }
  float4 wv[3], wn[3];
#pragma unroll
  for (int i = 0; i < 3; i++) wn[i] = wp[i * GT];

#pragma unroll
  for (int kkp = 0; kkp < KCH; kkp++) {
#pragma unroll
    for (int i = 0; i < 3; i++) wv[i] = wn[i];
    if (kkp < KCH - 1) {
#pragma unroll
      for (int i = 0; i < 3; i++) wn[i] = wp[((kkp + 1) * 3 + i) * GT];
    }
#pragma unroll
    for (int e = 0; e < 4; e++) {
      // [k][b], GB=4 -> one LDS.128 covers both batch pairs of this k.
      ulonglong2 v = *reinterpret_cast<const ulonglong2*>(
          act + (kkp * 4 + e) * 4);
#pragma unroll
      for (int g = 0; g < 3; g++) {
        ull w2 = dup2(comp(wv[g], e));
        ffma2(acc[g][0], w2, v.x);
        ffma2(acc[g][1], w2, v.y);
      }
    }
  }
}

// Combine owned batch-pair P: add the single partner contribution, GRU gate
// math, write new hidden state. P compile-time.
template <int P>
__device__ __forceinline__ void combine_pair(ull r2, ull z2, ull nx2, ull nh2,
                                             const ull* __restrict__ sp, int u,
                                             const float* __restrict__ sb,
                                             float* __restrict__ hl,
                                             float* __restrict__ sx) {
  const ull* base = sp + P * 512 + u;
  fadd2(r2,  base[0]);
  fadd2(z2,  base[128]);
  fadd2(nx2, base[256]);
  fadd2(nh2, base[384]);
  float brz_r = sb[u], brz_z = sb[128 + u];
  float bn_x = sb[256 + u], bn_h = sb[384 + u];
  float2 rr = unpk(r2), zz = unpk(z2), xx = unpk(nx2), hh = unpk(nh2);
  float2 hp = unpk(*reinterpret_cast<const ull*>(hl + u * 4 + 2 * P));
  float r0 = sigm(rr.x + brz_r), z0 = sigm(zz.x + brz_z);
  float n0 = tanh_fast(xx.x + bn_x + r0 * (hh.x + bn_h));
  float h0 = fmaf(z0, hp.x - n0, n0);
  float r1 = sigm(rr.y + brz_r), z1 = sigm(zz.y + brz_z);
  float n1 = tanh_fast(xx.y + bn_x + r1 * (hh.y + bn_h));
  float h1 = fmaf(z1, hp.y - n1, n1);
  ull o = pack2(h0, h1);
  *reinterpret_cast<ull*>(hl + u * 4 + 2 * P) = o;
  *reinterpret_cast<ull*>(sx + u * 4 + 2 * P) = o;
}

__global__ void __launch_bounds__(NTHR, 1)
gru_kernel(const float* __restrict__ hiddens,
           const float* __restrict__ b_ih,
           const float* __restrict__ b_hh,
           const float* __restrict__ fc_w,
           const float* __restrict__ fc_b,
           float* __restrict__ out) {
  __shared__ __align__(16) float s_x[2][H * GB];            // [grp][k][b]
  __shared__ __align__(16) float s_h[2][LAYERS * H * GB];   // [grp][l][k][b]
  __shared__ __align__(16) ull   s_p[2][2 * 4 * 128];       // [grp][P][v][u]
  __shared__ float s_fcw[2 * H];
  __shared__ float s_fcb[2];
  __shared__ float s_bias[LAYERS * 4 * 128];                // [l][v][u]

  const int tid = threadIdx.x;
  const int grp = tid >> 8;          // group (independent barrier domain)
  const int wt  = tid & 255;
  const int u   = wt & 127;
  const int kh  = wt >> 7;           // K-half & owned batch-pair
  const int b0g = blockIdx.x * 8 + grp * GB;
  const int bid = grp + 1;           // named barrier id

  if (tid < 128) {
#pragma unroll
    for (int l = 0; l < LAYERS; l++) {
      s_bias[l * 512 + 0 * 128 + tid] =
          b_ih[l * G3 + tid] + b_hh[l * G3 + tid];
      s_bias[l * 512 + 1 * 128 + tid] =
          b_ih[l * G3 + 128 + tid] + b_hh[l * G3 + 128 + tid];
      s_bias[l * 512 + 2 * 128 + tid] = b_ih[l * G3 + 256 + tid];
      s_bias[l * 512 + 3 * 128 + tid] = b_hh[l * G3 + 256 + tid];
    }
  }
  if (tid < 256) s_fcw[tid] = fc_w[tid];
  if (tid < 2)   s_fcb[tid] = fc_b[tid];

  // h init: hiddens[b][l][k] -> s_h[grp][l][k][b]
  for (int i = wt; i < LAYERS * H * GB; i += GT) {
    int l = i >> 9, rem = i & 511, k = rem >> 2, b = rem & 3;
    s_h[grp][i] = hiddens[(b0g + b) * (LAYERS * H) + l * H + k];
  }
  for (int i = wt; i < H * GB; i += GT) s_x[grp][i] = 0.0f;
  __syncthreads();   // whole CTA once; groups are independent afterwards

  // Prologue: W_hh half-gemv of cell 0 (layer 0).
  ull acch[3][2];
  half_gemv(s_h[grp] + kh * 256, g_whh + wt, acch);

  for (int t = 0; t < T; t++) {
#pragma unroll 1
    for (int l = 0; l < LAYERS; l++) {
      float* __restrict__ hl = s_h[grp] + l * (H * GB);

      // W_ih half-gemv of the current cell.
      ull accx[3][2];
      half_gemv(s_x[grp] + kh * 256, g_wih + l * (KCH * 3 * GT) + wt, accx);

      // Merge r,z across arrays (only sums matter).
      ull r0 = accx[0][0]; fadd2(r0, acch[0][0]);
      ull r1 = accx[0][1]; fadd2(r1, acch[0][1]);
      ull z0 = accx[1][0]; fadd2(z0, acch[1][0]);
      ull z1 = accx[1][1]; fadd2(z1, acch[1][1]);

      // Store the non-owned pair's partials (owner = kh).
      if (kh == 0) {
        ull* base = s_p[grp] + 512 + u;
        base[0]   = r1;
        base[128] = z1;
        base[256] = accx[2][1];
        base[384] = acch[2][1];
      } else {
        ull* base = s_p[grp] + u;
        base[0]   = r0;
        base[128] = z0;
        base[256] = accx[2][0];
        base[384] = acch[2][0];
      }
      gbar(bid);                                  // B1: partials visible

      // combine(i) then hGEMV(i+1); cross-group de-phasing fills the
      // combine trough with the other group's FFMA2 stream.
      const float* sb = s_bias + l * 512;
      if (kh == 0)
        combine_pair<0>(r0, z0, accx[2][0], acch[2][0], s_p[grp], u, sb,
                        hl, s_x[grp]);
      else
        combine_pair<1>(r1, z1, accx[2][1], acch[2][1], s_p[grp], u, sb,
                        hl, s_x[grp]);

      int ln = (l == LAYERS - 1) ? 0 : l + 1;     // next cell's layer
      half_gemv(s_h[grp] + ln * (H * GB) + kh * 256,
                g_whh + ln * (KCH * 3 * GT) + wt, acch);
      gbar(bid);                                  // B2: s_x visible

      // fc head: 8 outputs (2 out x 4 batch) x 16 lanes, within the group.
      if (l == 2 && wt < 128) {
        int oid = wt >> 4, s = wt & 15;
        int o = oid & 1, b = oid >> 1;
        float p = 0.0f;
#pragma unroll
        for (int m = 0; m < 8; m++)
          p = fmaf(s_fcw[o * H + s * 8 + m], s_x[grp][(s * 8 + m) * 4 + b], p);
        p += __shfl_down_sync(0xffffffffu, p, 8, 16);
        p += __shfl_down_sync(0xffffffffu, p, 4, 16);
        p += __shfl_down_sync(0xffffffffu, p, 2, 16);
        p += __shfl_down_sync(0xffffffffu, p, 1, 16);
        if (s == 0) out[((b0g + b) * T + t) * 2 + o] = p + s_fcb[o];
      }
      // fc reads of s_x precede the next cell's combine writes (those sit
      // behind the next cell's B1 in this group's barrier domain).
    }
  }
}

extern "C" void kernel_launch(void* const* d_in, const int* in_sizes, int n_in,
                              void* d_out, int out_size) {
  (void)in_sizes; (void)n_in; (void)out_size;
  const float* hiddens = (const float*)d_in[0];
  const float* W_ih    = (const float*)d_in[1];
  const float* W_hh    = (const float*)d_in[2];
  const float* b_ih    = (const float*)d_in[3];
  const float* b_hh    = (const float*)d_in[4];
  const float* fc_w    = (const float*)d_in[5];
  const float* fc_b    = (const float*)d_in[6];
  float* out = (float*)d_out;

  const int prep_elems = 2 * LAYERS * KCH * 3 * GT;
  prep_kernel<<<(prep_elems + 255) / 256, 256>>>(W_ih, W_hh);
  gru_kernel<<<NBLK, NTHR>>>(hiddens, b_ih, b_hh, fc_w, fc_b, out);
}

// round 16
// speedup vs baseline: 1.3613x; 1.3613x over previous
#include <cuda_runtime.h>
#include <cstdint>

// ----------------------------------------------------------------------------
// RNNDecoder: 3-layer GRU (H=128), T=256, B=1024, fc head (out=2).
//
// R14: weights streamed into a shared-memory ring by a PRODUCER WARP using
// cp.async.bulk (TMA) + mbarriers; compute warps read them via 29-cyc LDS
// instead of 234-600-cyc LDG. Diagnosis R3-R13: fma pinned ~49% and issue
// ~40% in every config while weight-LDG latency (inflated by L1tex queueing
// of 3072 wavefronts/cell) stalls all warps; register prefetch depth 1 can't
// cover it, but a 3x48KB ring (~2 chunks in flight) can.
//   - 128 CTAs x 288 threads: warps 0-7 compute (R8 structure: K-half split,
//     batch-pair f32x2, register gate-combine, bar.sync 1,256 x2 per cell),
//     warp 8 = producer (issues 8 bulk copies/cell, throttled by the ring).
//   - Chunk = 4 k-chunks x 3 gates x 256 threads x 16B = 48KB; full/empty
//     mbarrier pair per ring slot (full: producer expect_tx; empty: 8
//     per-warp arrivals). Producer cursor starts phase 1 (helper convention).
//   - L2 bytes unchanged -> clean discriminator for the L2-BW hypothesis.
// ----------------------------------------------------------------------------

namespace {
constexpr int LAYERS = 3;
constexpr int H      = 128;
constexpr int G3     = 3 * H;
constexpr int T      = 256;
constexpr int BC     = 8;
constexpr int NTHR   = 288;        // 8 compute warps + 1 producer warp
constexpr int CT     = 256;        // compute threads
constexpr int NBLK   = 128;        // 1024 / BC

constexpr int RING        = 3;
constexpr int CHUNK_BYTES = 49152; // 4 kkp x 3 gates x 256 t x 16B
constexpr int CHUNK_F4    = 3072;
constexpr int NCID        = 24;    // (l, arr) x 4 chunks

// dynamic smem layout (bytes)
constexpr int SMEM_RING = 0;                             // 147456
constexpr int SMEM_X    = SMEM_RING + RING * CHUNK_BYTES;// float[1024] [k][b]
constexpr int SMEM_H    = SMEM_X + 4096;                 // float[3072] [l][k][b]
constexpr int SMEM_P    = SMEM_H + 12288;                // ull[2048] exchange
constexpr int SMEM_BIAS = SMEM_P + 16384;                // float[1536] [l][v][u]
constexpr int SMEM_FCW  = SMEM_BIAS + 6144;              // float[256]
constexpr int SMEM_FCB  = SMEM_FCW + 1024;               // float[2]
constexpr int SMEM_MBAR = SMEM_FCB + 16;                 // full[3], empty[3]
constexpr int SMEM_TOTAL = SMEM_MBAR + 64;               // 187536
}

typedef unsigned long long ull;

// Pre-transposed weights, chunk-contiguous:
// cid = (l*2 + arr)*4 + c ; within chunk: [kk4][g][t] float4,
// t = kh*128 + u, absolute k4 = kh*16 + (c*4 + kk4).
__device__ float4 g_wt[NCID * CHUNK_F4];

__global__ void prep_kernel(const float* __restrict__ wih,
                            const float* __restrict__ whh) {
  int idx = blockIdx.x * blockDim.x + threadIdx.x;
  if (idx >= NCID * CHUNK_F4) return;
  int cid = idx / CHUNK_F4;
  int e   = idx % CHUNK_F4;
  int t   = e & 255;
  int g   = (e >> 8) % 3;
  int kk4 = e / 768;
  int c   = cid & 3;
  int la  = cid >> 2;
  int arr = la & 1, l = la >> 1;
  int kh  = t >> 7, u = t & 127;
  int k4  = kh * 16 + (c * 4 + kk4);
  const float* src =
      (arr ? whh : wih) + (l * G3 + g * 128 + u) * H + k4 * 4;
  g_wt[idx] = *reinterpret_cast<const float4*>(src);
}

__device__ __forceinline__ uint32_t smem_u32(const void* p) {
  uint32_t a;
  asm("{ .reg .u64 t; cvta.to.shared.u64 t, %1; cvt.u32.u64 %0, t; }"
      : "=r"(a) : "l"(p));
  return a;
}
#define MBAR_INIT(a, n) \
  asm volatile("mbarrier.init.shared.b64 [%0], %1;" :: "r"(a), "r"(n) : "memory")
#define MBAR_ARRIVE(a) \
  asm volatile("mbarrier.arrive.shared.b64 _, [%0];" :: "r"(a) : "memory")
#define MBAR_EXPECT_TX(a, n) \
  asm volatile("mbarrier.arrive.expect_tx.shared.b64 _, [%0], %1;" \
               :: "r"(a), "r"(n) : "memory")
#define BULK_G2S(dst, src, n, mbar) \
  asm volatile("cp.async.bulk.shared::cta.global.mbarrier::complete_tx::bytes" \
               " [%0], [%1], %2, [%3];" \
               :: "r"(dst), "l"(src), "r"(n), "r"(mbar) : "memory")
#define MBAR_WAITP(a, ph) do {                                              \
  uint32_t _d;                                                              \
  asm volatile("{\n\t.reg .pred p;\n\t"                                     \
    "mbarrier.try_wait.parity.acquire.cta.shared::cta.b64 p, [%1], %2;\n\t" \
    "selp.b32 %0, 1, 0, p;\n\t}"                                            \
    : "=r"(_d) : "r"(a), "r"(ph) : "memory");                               \
  while (!_d) {                                                             \
    asm volatile("{\n\t.reg .pred p;\n\t"                                   \
      "mbarrier.try_wait.parity.acquire.cta.shared::cta.b64 p, [%1], %2, 0x989680;\n\t" \
      "selp.b32 %0, 1, 0, p;\n\t}"                                          \
      : "=r"(_d) : "r"(a), "r"(ph) : "memory");                             \
  }                                                                         \
} while (0)

__device__ __forceinline__ void ffma2(ull& a, ull w, ull x) {
  asm("fma.rn.f32x2 %0, %1, %2, %0;" : "+l"(a) : "l"(w), "l"(x));
}
__device__ __forceinline__ void fadd2(ull& a, ull b) {
  asm("add.rn.f32x2 %0, %0, %1;" : "+l"(a) : "l"(b));
}
__device__ __forceinline__ ull dup2(float w) {
  ull r;
  asm("mov.b64 %0, {%1, %1};" : "=l"(r) : "f"(w));
  return r;
}
__device__ __forceinline__ float2 unpk(ull v) {
  float lo, hi;
  asm("mov.b64 {%0, %1}, %2;" : "=f"(lo), "=f"(hi) : "l"(v));
  return make_float2(lo, hi);
}
__device__ __forceinline__ ull pack2(float lo, float hi) {
  ull r;
  asm("mov.b64 %0, {%1, %2};" : "=l"(r) : "f"(lo), "f"(hi));
  return r;
}
__device__ __forceinline__ float sigm(float x) {
  return __fdividef(1.0f, 1.0f + __expf(-x));
}
__device__ __forceinline__ float tanh_fast(float v) {
  float a = fabsf(v);
  float e = __expf(-2.0f * a);
  float r = __fdividef(1.0f - e, 1.0f + e);
  return copysignf(r, v);
}
__device__ __forceinline__ float comp(const float4& v, int e) {
  return e == 0 ? v.x : e == 1 ? v.y : e == 2 ? v.z : v.w;
}
__device__ __forceinline__ void cbar() {           // compute-warps barrier
  asm volatile("bar.sync 1, %0;" :: "r"(CT) : "memory");
}

// One array's gemv over this thread's K-half, consuming 4 ring chunks.
// acc[g][q]: 3 gates x 4 batch-pairs. Weights via LDS from the staged ring.
__device__ __forceinline__ void gemv_ring(char* dsm,
                                          const float* __restrict__ act,
                                          int t, int& cs, int& cp,
                                          ull (&acc)[3][4]) {
#pragma unroll
  for (int g = 0; g < 3; g++)
#pragma unroll
    for (int q = 0; q < 4; q++) acc[g][q] = 0ull;

  const uint32_t mb0 = smem_u32(dsm + SMEM_MBAR);
#pragma unroll
  for (int c = 0; c < 4; c++) {
    MBAR_WAITP(mb0 + cs * 8, cp);                  // full[cs]
    const float4* wb = reinterpret_cast<const float4*>(
        dsm + SMEM_RING + cs * CHUNK_BYTES);
#pragma unroll
    for (int kk4 = 0; kk4 < 4; kk4++) {
      float4 w0 = wb[(kk4 * 3 + 0) * 256 + t];
      float4 w1 = wb[(kk4 * 3 + 1) * 256 + t];
      float4 w2 = wb[(kk4 * 3 + 2) * 256 + t];
#pragma unroll
      for (int e = 0; e < 4; e++) {
        int k8 = ((c * 4 + kk4) * 4 + e) * 8;
        ulonglong2 v0 = *reinterpret_cast<const ulonglong2*>(act + k8);
        ulonglong2 v1 = *reinterpret_cast<const ulonglong2*>(act + k8 + 4);
        ull wr = dup2(comp(w0, e));
        ffma2(acc[0][0], wr, v0.x); ffma2(acc[0][1], wr, v0.y);
        ffma2(acc[0][2], wr, v1.x); ffma2(acc[0][3], wr, v1.y);
        ull wz = dup2(comp(w1, e));
        ffma2(acc[1][0], wz, v0.x); ffma2(acc[1][1], wz, v0.y);
        ffma2(acc[1][2], wz, v1.x); ffma2(acc[1][3], wz, v1.y);
        ull wn = dup2(comp(w2, e));
        ffma2(acc[2][0], wn, v0.x); ffma2(acc[2][1], wn, v0.y);
        ffma2(acc[2][2], wn, v1.x); ffma2(acc[2][3], wn, v1.y);
      }
    }
    if ((threadIdx.x & 31) == 0)
      MBAR_ARRIVE(mb0 + 24 + cs * 8);              // empty[cs], count=8
    cs++;
    if (cs == RING) { cs = 0; cp ^= 1; }
  }
}

// Combine owned pairs P0,P0+1: add partner partials, GRU gate math, write h.
template <int P0>
__device__ __forceinline__ void combine2(const ull (&rzr)[4], const ull (&rzz)[4],
                                         const ull (&accx)[3][4],
                                         const ull (&acch)[3][4],
                                         const ull* __restrict__ reg, int u,
                                         const float* __restrict__ sb,
                                         float* __restrict__ hl,
                                         float* __restrict__ sx) {
#pragma unroll
  for (int pp = 0; pp < 2; pp++) {
    const int P = P0 + pp;
    ull r2 = rzr[P];       fadd2(r2,  reg[(0 * 2 + pp) * 128 + u]);
    ull z2 = rzz[P];       fadd2(z2,  reg[(1 * 2 + pp) * 128 + u]);
    ull nx2 = accx[2][P];  fadd2(nx2, reg[(2 * 2 + pp) * 128 + u]);
    ull nh2 = acch[2][P];  fadd2(nh2, reg[(3 * 2 + pp) * 128 + u]);
    float brz_r = sb[u], brz_z = sb[128 + u];
    float bn_x = sb[256 + u], bn_h = sb[384 + u];
    float2 rr = unpk(r2), zz = unpk(z2), xx = unpk(nx2), hh = unpk(nh2);
    float2 hp = unpk(*reinterpret_cast<const ull*>(hl + u * 8 + 2 * P));
    float r0 = sigm(rr.x + brz_r), z0 = sigm(zz.x + brz_z);
    float n0 = tanh_fast(xx.x + bn_x + r0 * (hh.x + bn_h));
    float h0 = fmaf(z0, hp.x - n0, n0);
    float r1 = sigm(rr.y + brz_r), z1 = sigm(zz.y + brz_z);
    float n1 = tanh_fast(xx.y + bn_x + r1 * (hh.y + bn_h));
    float h1 = fmaf(z1, hp.y - n1, n1);
    ull o = pack2(h0, h1);
    *reinterpret_cast<ull*>(hl + u * 8 + 2 * P) = o;
    *reinterpret_cast<ull*>(sx + u * 8 + 2 * P) = o;
  }
}

__global__ void __launch_bounds__(NTHR, 1)
gru_kernel(const float* __restrict__ hiddens,
           const float* __restrict__ b_ih,
           const float* __restrict__ b_hh,
           const float* __restrict__ fc_w,
           const float* __restrict__ fc_b,
           float* __restrict__ out) {
  extern __shared__ __align__(16) char dsm[];
  float* s_x    = reinterpret_cast<float*>(dsm + SMEM_X);
  float* s_h    = reinterpret_cast<float*>(dsm + SMEM_H);
  ull*   s_p    = reinterpret_cast<ull*>(dsm + SMEM_P);
  float* s_bias = reinterpret_cast<float*>(dsm + SMEM_BIAS);
  float* s_fcw  = reinterpret_cast<float*>(dsm + SMEM_FCW);
  float* s_fcb  = reinterpret_cast<float*>(dsm + SMEM_FCB);
  const uint32_t mb0 = smem_u32(dsm + SMEM_MBAR);

  const int tid = threadIdx.x;
  const int b0  = blockIdx.x * BC;

  // ---- shared init (all 288 threads) ----
  if (tid < 128) {
#pragma unroll
    for (int l = 0; l < LAYERS; l++) {
      s_bias[l * 512 + 0 * 128 + tid] =
          b_ih[l * G3 + tid] + b_hh[l * G3 + tid];
      s_bias[l * 512 + 1 * 128 + tid] =
          b_ih[l * G3 + 128 + tid] + b_hh[l * G3 + 128 + tid];
      s_bias[l * 512 + 2 * 128 + tid] = b_ih[l * G3 + 256 + tid];
      s_bias[l * 512 + 3 * 128 + tid] = b_hh[l * G3 + 256 + tid];
    }
  }
  if (tid < 256) s_fcw[tid] = fc_w[tid];
  if (tid < 2)   s_fcb[tid] = fc_b[tid];
  for (int i = tid; i < LAYERS * H * BC; i += NTHR) {
    int l = i >> 10, rem = i & 1023, k = rem >> 3, b = rem & 7;
    s_h[i] = hiddens[(b0 + b) * (LAYERS * H) + l * H + k];
  }
  for (int i = tid; i < H * BC; i += NTHR) s_x[i] = 0.0f;
  if (tid == 0) {
#pragma unroll
    for (int s = 0; s < RING; s++) {
      MBAR_INIT(mb0 + s * 8, 1);            // full[s]: producer expect_tx
      MBAR_INIT(mb0 + 24 + s * 8, 8);       // empty[s]: 8 compute warps
    }
  }
  __syncthreads();

  if (tid >= 256) {
    // ---------------- producer warp ----------------
    if ((tid & 31) == 0) {
      int ps = 0, pp = 1;                   // producer cursor, phase 1
      const char* gw = reinterpret_cast<const char*>(g_wt);
      const uint32_t ring0 = smem_u32(dsm + SMEM_RING);
      // prologue: W_hh layer 0 (cid base 4)
      for (int c = 0; c < 4; c++) {
        MBAR_WAITP(mb0 + 24 + ps * 8, pp);
        MBAR_EXPECT_TX(mb0 + ps * 8, (uint32_t)CHUNK_BYTES);
        BULK_G2S(ring0 + ps * CHUNK_BYTES,
                 (uint64_t)(gw + (4 + c) * CHUNK_BYTES),
                 (uint32_t)CHUNK_BYTES, mb0 + ps * 8);
        if (++ps == RING) { ps = 0; pp ^= 1; }
      }
      for (int t = 0; t < T; t++) {
        for (int l = 0; l < LAYERS; l++) {
          int ln = (l == LAYERS - 1) ? 0 : l + 1;
          for (int j = 0; j < 8; j++) {
            int cid = (j < 4) ? (l * 8 + j) : (ln * 8 + 4 + (j - 4));
            MBAR_WAITP(mb0 + 24 + ps * 8, pp);
            MBAR_EXPECT_TX(mb0 + ps * 8, (uint32_t)CHUNK_BYTES);
            BULK_G2S(ring0 + ps * CHUNK_BYTES,
                     (uint64_t)(gw + cid * CHUNK_BYTES),
                     (uint32_t)CHUNK_BYTES, mb0 + ps * 8);
            if (++ps == RING) { ps = 0; pp ^= 1; }
          }
        }
      }
    }
    return;
  }

  // ---------------- compute warps (tid 0..255) ----------------
  const int u  = tid & 127;
  const int kh = tid >> 7;                  // K-half; owns pairs 2kh, 2kh+1
  int cs = 0, cp = 0;                       // consumer ring cursor

  // Prologue: W_hh half-gemv of cell 0 (layer 0).
  ull acch[3][4];
  gemv_ring(dsm, s_h + kh * 512, tid, cs, cp, acch);

  for (int t = 0; t < T; t++) {
#pragma unroll 1
    for (int l = 0; l < LAYERS; l++) {
      float* __restrict__ hl = s_h + l * (H * BC);

      // W_ih half-gemv of the current cell.
      ull accx[3][4];
      gemv_ring(dsm, s_x + kh * 512, tid, cs, cp, accx);

      // Merge r,z across arrays (only sums matter).
      ull rzr[4], rzz[4];
#pragma unroll
      for (int q = 0; q < 4; q++) {
        rzr[q] = accx[0][q]; fadd2(rzr[q], acch[0][q]);
        rzz[q] = accx[1][q]; fadd2(rzz[q], acch[1][q]);
      }

      // Exchange: kh0 stores pairs 2,3 (region B); kh1 stores 0,1 (region A).
      if (kh == 0) {
        ull* rb = s_p + 1024;
#pragma unroll
        for (int pp = 0; pp < 2; pp++) {
          rb[(0 * 2 + pp) * 128 + u] = rzr[2 + pp];
          rb[(1 * 2 + pp) * 128 + u] = rzz[2 + pp];
          rb[(2 * 2 + pp) * 128 + u] = accx[2][2 + pp];
          rb[(3 * 2 + pp) * 128 + u] = acch[2][2 + pp];
        }
      } else {
        ull* ra = s_p;
#pragma unroll
        for (int pp = 0; pp < 2; pp++) {
          ra[(0 * 2 + pp) * 128 + u] = rzr[pp];
          ra[(1 * 2 + pp) * 128 + u] = rzz[pp];
          ra[(2 * 2 + pp) * 128 + u] = accx[2][pp];
          ra[(3 * 2 + pp) * 128 + u] = acch[2][pp];
        }
      }
      cbar();                                // B1

      const float* sb = s_bias + l * 512;
      if (kh == 0)
        combine2<0>(rzr, rzz, accx, acch, s_p, u, sb, hl, s_x);
      else
        combine2<2>(rzr, rzz, accx, acch, s_p + 1024, u, sb, hl, s_x);

      // Pipelined W_hh half-gemv for the next cell.
      int ln = (l == LAYERS - 1) ? 0 : l + 1;
      gemv_ring(dsm, s_h + ln * (H * BC) + kh * 512, tid, cs, cp, acch);
      cbar();                                // B2

      // fc head: 16 outputs (2 out x 8 batch) x 16 lanes.
      if (l == 2) {
        int oid = tid >> 4, s = tid & 15;
        int o = oid & 1, b = oid >> 1;
        float p = 0.0f;
#pragma unroll
        for (int m = 0; m < 8; m++)
          p = fmaf(s_fcw[o * H + s * 8 + m], s_x[(s * 8 + m) * 8 + b], p);
        p += __shfl_down_sync(0xffffffffu, p, 8, 16);
        p += __shfl_down_sync(0xffffffffu, p, 4, 16);
        p += __shfl_down_sync(0xffffffffu, p, 2, 16);
        p += __shfl_down_sync(0xffffffffu, p, 1, 16);
        if (s == 0) out[((b0 + b) * T + t) * 2 + o] = p + s_fcb[o];
      }
    }
  }
}

extern "C" void kernel_launch(void* const* d_in, const int* in_sizes, int n_in,
                              void* d_out, int out_size) {
  (void)in_sizes; (void)n_in; (void)out_size;
  const float* hiddens = (const float*)d_in[0];
  const float* W_ih    = (const float*)d_in[1];
  const float* W_hh    = (const float*)d_in[2];
  const float* b_ih    = (const float*)d_in[3];
  const float* b_hh    = (const float*)d_in[4];
  const float* fc_w    = (const float*)d_in[5];
  const float* fc_b    = (const float*)d_in[6];
  float* out = (float*)d_out;

  cudaFuncSetAttribute(gru_kernel, cudaFuncAttributeMaxDynamicSharedMemorySize,
                       SMEM_TOTAL);

  const int prep_elems = NCID * CHUNK_F4;
  prep_kernel<<<(prep_elems + 255) / 256, 256>>>(W_ih, W_hh);
  gru_kernel<<<NBLK, NTHR, SMEM_TOTAL>>>(hiddens, b_ih, b_hh, fc_w, fc_b, out);
}